// round 12
// baseline (speedup 1.0000x reference)
#include <cuda_runtime.h>
#include <cuda_fp16.h>
#include <cstdint>

// ---------------------------------------------------------------------------
// Problem constants
// ---------------------------------------------------------------------------
#define S_LEN   512
#define BATCH   64
#define EDIM    1024
#define HDIM    1024
#define NGATE   4096
#define MTOT    (S_LEN*BATCH)

#define OUT_HID  (67108864ull)
#define OUT_CELL (67108864ull + 131072ull)

// ---------------------------------------------------------------------------
// Static device scratch (fp16 2-pass: activations single, weights hi/lo split)
// ---------------------------------------------------------------------------
__device__ __half g_A[(size_t)MTOT * EDIM];
__device__ __half g_WxThi[2ull * NGATE * EDIM];          // [dir][n][k]
__device__ __half g_WxTlo[2ull * NGATE * EDIM];
__device__ __half g_WhThi[2ull * NGATE * HDIM];
__device__ __half g_WhTlo[2ull * NGATE * HDIM];
__device__ float  g_Gx[2ull * S_LEN * BATCH * NGATE];    // [dir][s][b][n]
__device__ __half g_h[2 * 2 * BATCH * HDIM];             // [buf][dir][b][h]
__device__ unsigned g_bar[2];

// ---------------------------------------------------------------------------
// PTX helpers
// ---------------------------------------------------------------------------
__device__ __forceinline__ uint32_t smem_u32(const void* p) {
    return (uint32_t)__cvta_generic_to_shared(p);
}
__device__ __forceinline__ void cp16(void* dst, const void* src) {
    asm volatile("cp.async.cg.shared.global [%0], [%1], 16;\n"
                 :: "r"(smem_u32(dst)), "l"(src));
}
__device__ __forceinline__ void cp_commit() { asm volatile("cp.async.commit_group;\n"); }
template <int N>
__device__ __forceinline__ void cp_wait() { asm volatile("cp.async.wait_group %0;\n" :: "n"(N)); }

__device__ __forceinline__ void ldsm4(uint32_t r[4], uint32_t addr) {
    asm volatile("ldmatrix.sync.aligned.m8n8.x4.shared.b16 {%0,%1,%2,%3}, [%4];\n"
                 : "=r"(r[0]), "=r"(r[1]), "=r"(r[2]), "=r"(r[3]) : "r"(addr));
}
__device__ __forceinline__ void mma_f16(float c[4], const uint32_t a[4], const uint32_t b[2]) {
    asm volatile(
        "mma.sync.aligned.m16n8k16.row.col.f32.f16.f16.f32 "
        "{%0,%1,%2,%3}, {%4,%5,%6,%7}, {%8,%9}, {%0,%1,%2,%3};\n"
        : "+f"(c[0]), "+f"(c[1]), "+f"(c[2]), "+f"(c[3])
        : "r"(a[0]), "r"(a[1]), "r"(a[2]), "r"(a[3]), "r"(b[0]), "r"(b[1]));
}
__device__ __forceinline__ float sigf(float x) { return 1.0f / (1.0f + expf(-x)); }

// ---------------------------------------------------------------------------
// K0: zero state + barrier counters
// ---------------------------------------------------------------------------
__global__ void k_init() {
    int i = blockIdx.x * 256 + threadIdx.x;
    if (i < 2 * 2 * BATCH * HDIM) g_h[i] = __float2half(0.0f);
    if (i < 2) g_bar[i] = 0u;
}

// ---------------------------------------------------------------------------
// K1: embedding gather -> fp16.  Row m = s*64+b
// ---------------------------------------------------------------------------
__global__ void k_embed(const int* __restrict__ inputs, const float* __restrict__ table) {
    int idx = blockIdx.x * 256 + threadIdx.x;
    int m  = idx >> 8;
    int kk = (idx & 255) * 4;
    int s = m >> 6, b = m & 63;
    int tok = inputs[b * S_LEN + s];
    float4 v = *(const float4*)(table + (size_t)tok * EDIM + kk);
    size_t o = (size_t)m * EDIM + kk;
    *(__half2*)(g_A + o)     = __half2(__float2half(v.x), __float2half(v.y));
    *(__half2*)(g_A + o + 2) = __half2(__float2half(v.z), __float2half(v.w));
}

// ---------------------------------------------------------------------------
// K2: weight transpose + fp16 hi/lo split.  W[k][n] -> WT_hi/lo[n][k]
// ---------------------------------------------------------------------------
__global__ void k_wsplit(const float* __restrict__ w0, const float* __restrict__ w1,
                         const float* __restrict__ w2, const float* __restrict__ w3) {
    __shared__ float tile[32][33];
    int z = blockIdx.z;
    const float* W = (z == 0) ? w0 : (z == 1) ? w1 : (z == 2) ? w2 : w3;
    __half* Ohi = ((z & 1) ? g_WhThi : g_WxThi) + (size_t)(z >> 1) * NGATE * EDIM;
    __half* Olo = ((z & 1) ? g_WhTlo : g_WxTlo) + (size_t)(z >> 1) * NGATE * EDIM;
    int tx = threadIdx.x, ty = threadIdx.y;
    int n0 = blockIdx.x * 32, k0 = blockIdx.y * 32;
#pragma unroll
    for (int i = 0; i < 4; i++)
        tile[ty + i * 8][tx] = W[(size_t)(k0 + ty + i * 8) * NGATE + n0 + tx];
    __syncthreads();
#pragma unroll
    for (int i = 0; i < 4; i++) {
        int n = n0 + ty + i * 8;
        int k = k0 + tx;
        float v = tile[tx][ty + i * 8];
        __half hi = __float2half(v);
        Ohi[(size_t)n * EDIM + k] = hi;
        Olo[(size_t)n * EDIM + k] = __float2half(v - __half2float(hi));
    }
}

// ---------------------------------------------------------------------------
// K3: prefill GEMM  Gx[dir] = A @ WxT(dir)   (fp16 2-pass)
// 128x128 tile, BK=32, 3-stage ring (90KB, 2 CTAs/SM), single sync per chunk.
// ---------------------------------------------------------------------------
#define P_SA   40
#define P_ARR  (128 * P_SA)
#define P_STG  (3 * P_ARR)
#define P_SMEM (3 * P_STG * 2)

__device__ __forceinline__ void prefill_load(
    __half* base, const __half* gBhi, const __half* gBlo,
    int tid, int m0, int n0, int k0)
{
#pragma unroll
    for (int j = 0; j < 2; j++) {
        int it = tid + j * 256;
        int r = it >> 2, ch = it & 3;
        size_t offA = (size_t)(m0 + r) * EDIM + k0 + ch * 8;
        cp16(base + r * P_SA + ch * 8, g_A + offA);
        size_t offB = (size_t)(n0 + r) * EDIM + k0 + ch * 8;
        cp16(base + P_ARR + r * P_SA + ch * 8,     gBhi + offB);
        cp16(base + 2 * P_ARR + r * P_SA + ch * 8, gBlo + offB);
    }
}

__global__ void __launch_bounds__(256, 2) k_prefill() {
    extern __shared__ __align__(16) char smraw[];
    __half* sm = (__half*)smraw;

    int tid = threadIdx.x, lane = tid & 31, warp = tid >> 5;
    int wm = warp >> 1, wn = warp & 1;
    int dir = blockIdx.z;
    int m0 = blockIdx.y * 128, n0 = blockIdx.x * 128;
    const __half* gBhi = g_WxThi + (size_t)dir * NGATE * EDIM;
    const __half* gBlo = g_WxTlo + (size_t)dir * NGATE * EDIM;

    int l8 = lane & 7, sel = lane >> 3;
    int aRow = wm * 32 + (lane & 15);
    int aK   = (lane >> 4) * 8;
    int bRow = wn * 64 + (sel >> 1) * 8 + l8;
    int bK   = (sel & 1) * 8;

    float acc[2][8][4];
#pragma unroll
    for (int a = 0; a < 2; a++)
#pragma unroll
        for (int b = 0; b < 8; b++)
#pragma unroll
            for (int c = 0; c < 4; c++) acc[a][b][c] = 0.0f;

    const int KT = EDIM / 32;   // 32
    prefill_load(sm,         gBhi, gBlo, tid, m0, n0, 0);
    cp_commit();
    prefill_load(sm + P_STG, gBhi, gBlo, tid, m0, n0, 32);
    cp_commit();

#pragma unroll 1
    for (int kt = 0; kt < KT; kt++) {
        cp_wait<1>();
        __syncthreads();
        if (kt + 2 < KT)
            prefill_load(sm + ((kt + 2) % 3) * P_STG, gBhi, gBlo, tid, m0, n0, (kt + 2) * 32);
        cp_commit();

        __half* base = sm + (kt % 3) * P_STG;
        uint32_t aB  = smem_u32(base);
        uint32_t bHb = aB + P_ARR * 2;
        uint32_t bLb = aB + 2 * P_ARR * 2;

#pragma unroll
        for (int ks = 0; ks < 32; ks += 16) {
            uint32_t ah[2][4];
#pragma unroll
            for (int mt = 0; mt < 2; mt++) {
                uint32_t ao = ((aRow + mt * 16) * P_SA + ks + aK) * 2;
                ldsm4(ah[mt], aB + ao);
            }
#pragma unroll
            for (int np = 0; np < 4; np++) {
                uint32_t bo = ((bRow + np * 16) * P_SA + ks + bK) * 2;
                uint32_t bh4[4], bl4[4];
                ldsm4(bh4, bHb + bo);
                ldsm4(bl4, bLb + bo);
#pragma unroll
                for (int mt = 0; mt < 2; mt++) {
                    mma_f16(acc[mt][np*2],   ah[mt], bh4 + 0);
                    mma_f16(acc[mt][np*2],   ah[mt], bl4 + 0);
                    mma_f16(acc[mt][np*2+1], ah[mt], bh4 + 2);
                    mma_f16(acc[mt][np*2+1], ah[mt], bl4 + 2);
                }
            }
        }
    }

    float* C = g_Gx + (size_t)dir * S_LEN * BATCH * NGATE;
#pragma unroll
    for (int mt = 0; mt < 2; mt++) {
#pragma unroll
        for (int nt = 0; nt < 8; nt++) {
            int row = m0 + wm * 32 + mt * 16 + (lane >> 2);
            int col = n0 + wn * 64 + nt * 8 + 2 * (lane & 3);
            *(float2*)(C + (size_t)row * NGATE + col)       = make_float2(acc[mt][nt][0], acc[mt][nt][1]);
            *(float2*)(C + (size_t)(row + 8) * NGATE + col) = make_float2(acc[mt][nt][2], acc[mt][nt][3]);
        }
    }
}

// ---------------------------------------------------------------------------
// K4: persistent recurrence.  128 CTAs (64/dir), 256 thr, resident wH.
// SPLIT RINGS: wL ring (time-invariant — chunks 0-2 of step t+1 prefetched
// BEFORE the grid barrier) and h ring (barrier-dependent, 8KB stages only).
// Uniform cp_wait<2> (groups complete FIFO; needed group is 3rd-from-tail).
// ---------------------------------------------------------------------------
#define RES_W  131072                       // resident wH (16 chunks x 8KB)
#define WL_OFF RES_W                        // wL ring: 4 x 8KB
#define H_OFF  (RES_W + 32768)              // h  ring: 4 x 8KB
#define R_SMEM (RES_W + 65536)              // 196608

__device__ __forceinline__ int r_grow(int r, int hu_base) {
    return ((r >> 3) & 3) * HDIM + hu_base + ((r & 7) | ((r >> 5) << 3));
}
__device__ __forceinline__ uint32_t r_sw(int r, int u) {
    return (uint32_t)(r * 128 + ((u ^ (r & 7)) << 4));
}

__device__ __forceinline__ void r_load_h(char* stg, const __half* hs, int tid, int k0) {
#pragma unroll
    for (int j = 0; j < 2; j++) {
        int it = tid + j * 256;
        int r = it >> 3, ch = it & 7;
        cp16(stg + r_sw(r, ch), hs + (size_t)r * HDIM + k0 + ch * 8);
    }
}
__device__ __forceinline__ void r_load_wl(char* stg, const __half* wL, int tid,
                                          int hu_base, int k0) {
#pragma unroll
    for (int j = 0; j < 2; j++) {
        int it = tid + j * 256;
        int r = it >> 3, ch = it & 7;
        cp16(stg + r_sw(r, ch), wL + (size_t)r_grow(r, hu_base) * HDIM + k0 + ch * 8);
    }
}

__global__ void __launch_bounds__(256, 1) k_recur(const float* __restrict__ bias_f,
                                                  const float* __restrict__ bias_b,
                                                  float* __restrict__ out) {
    extern __shared__ __align__(16) char smraw[];

    int tid = threadIdx.x, lane = tid & 31, warp = tid >> 5;
    int wm = warp >> 1, wn = warp & 1;            // 4 m-warps x 2 n-warps
    int dir = blockIdx.x >> 6;
    int hu_base = (blockIdx.x & 63) * 16;

    const __half* wH = g_WhThi + (size_t)dir * NGATE * HDIM;
    const __half* wL = g_WhTlo + (size_t)dir * NGATE * HDIM;
    const float* bias = dir ? bias_b : bias_f;

    int l8 = lane & 7, sel = lane >> 3;
    int aRow = wm * 16 + (lane & 15);
    int aK   = (lane >> 4) * 8;
    int bRow = wn * 32 + (sel >> 1) * 8 + l8;
    int bK   = (sel & 1) * 8;

    int hu0 = hu_base + wn * 8 + 2 * (lane & 3);
    float2 bs[4];
#pragma unroll
    for (int g = 0; g < 4; g++)
        bs[g] = *(const float2*)(bias + g * HDIM + hu0);

    // ---- prologue: resident Wh-hi (16 chunks x 64 rows x 64 k) ----
    for (int slot = tid; slot < 16 * 512; slot += 256) {
        int c = slot >> 9, r = (slot >> 3) & 63, ch = slot & 7;
        cp16(smraw + c * 8192 + r_sw(r, ch),
             wH + (size_t)r_grow(r, hu_base) * HDIM + c * 64 + ch * 8);
    }
    cp_commit();
    cp_wait<0>();
    __syncthreads();

    // initial wL prefetch for step 0, chunks 0..2
    r_load_wl(smraw + WL_OFF,            wL, tid, hu_base, 0);   cp_commit();
    r_load_wl(smraw + WL_OFF + 8192,     wL, tid, hu_base, 64);  cp_commit();
    r_load_wl(smraw + WL_OFF + 16384,    wL, tid, hu_base, 128); cp_commit();

    float creg[4] = {0.f, 0.f, 0.f, 0.f};

#pragma unroll 1
    for (int t = 0; t < S_LEN; t++) {
        const __half* hs = g_h + (size_t)((t & 1) * 2 + dir) * BATCH * HDIM;

        int srow = dir ? (S_LEN - 1 - t) : t;
        const float* Gx = g_Gx + ((size_t)dir * S_LEN + srow) * BATCH * NGATE;
        float2 gx[2][4];
#pragma unroll
        for (int k = 0; k < 2; k++) {
            int b = wm * 16 + (lane >> 2) + k * 8;
#pragma unroll
            for (int g = 0; g < 4; g++)
                gx[k][g] = *(const float2*)(Gx + (size_t)b * NGATE + g * HDIM + hu0);
        }

        r_load_h(smraw + H_OFF,         hs, tid, 0);   cp_commit();
        r_load_h(smraw + H_OFF + 8192,  hs, tid, 64);  cp_commit();
        r_load_h(smraw + H_OFF + 16384, hs, tid, 128); cp_commit();

        float acc[4][4];
#pragma unroll
        for (int g = 0; g < 4; g++)
#pragma unroll
            for (int c = 0; c < 4; c++) acc[g][c] = 0.0f;

        const int KT = HDIM / 64;   // 16
#pragma unroll 1
        for (int kt = 0; kt < KT; kt++) {
            cp_wait<2>();
            __syncthreads();
            if (kt + 3 < KT) {
                int s = (kt + 3) & 3;
                r_load_wl(smraw + WL_OFF + s * 8192, wL, tid, hu_base, (kt + 3) * 64);
                r_load_h (smraw + H_OFF  + s * 8192, hs, tid, (kt + 3) * 64);
            }
            cp_commit();

            uint32_t resb = smem_u32(smraw) + kt * 8192;
            uint32_t aB   = smem_u32(smraw + H_OFF  + (kt & 3) * 8192);
            uint32_t bLb  = smem_u32(smraw + WL_OFF + (kt & 3) * 8192);

#pragma unroll
            for (int ks = 0; ks < 64; ks += 16) {
                uint32_t ao = r_sw(aRow, (ks + aK) >> 3);
                uint32_t ah[4];
                ldsm4(ah, aB + ao);
#pragma unroll
                for (int np = 0; np < 2; np++) {
                    int br = bRow + np * 16;
                    uint32_t bo = r_sw(br, (ks + bK) >> 3);
                    uint32_t bh4[4], bl4[4];
                    ldsm4(bh4, resb + bo);
                    ldsm4(bl4, bLb + bo);
                    mma_f16(acc[np*2],   ah, bh4 + 0);
                    mma_f16(acc[np*2],   ah, bl4 + 0);
                    mma_f16(acc[np*2+1], ah, bh4 + 2);
                    mma_f16(acc[np*2+1], ah, bl4 + 2);
                }
            }
        }

        // ---- prefetch wL chunks 0..2 for step t+1 (hides behind barrier) ----
        r_load_wl(smraw + WL_OFF,         wL, tid, hu_base, 0);   cp_commit();
        r_load_wl(smraw + WL_OFF + 8192,  wL, tid, hu_base, 64);  cp_commit();
        r_load_wl(smraw + WL_OFF + 16384, wL, tid, hu_base, 128); cp_commit();

        // ---- fused LSTM update ----
        __half* hd = g_h + (size_t)(((t + 1) & 1) * 2 + dir) * BATCH * HDIM;

#pragma unroll
        for (int k = 0; k < 2; k++) {
            int b = wm * 16 + (lane >> 2) + k * 8;
            float hn[2], cn[2];
#pragma unroll
            for (int e = 0; e < 2; e++) {
                int j = k * 2 + e;
                float vi = acc[0][j] + (e ? gx[k][0].y : gx[k][0].x) + (e ? bs[0].y : bs[0].x);
                float vf = acc[1][j] + (e ? gx[k][1].y : gx[k][1].x) + (e ? bs[1].y : bs[1].x);
                float vg = acc[2][j] + (e ? gx[k][2].y : gx[k][2].x) + (e ? bs[2].y : bs[2].x);
                float vo = acc[3][j] + (e ? gx[k][3].y : gx[k][3].x) + (e ? bs[3].y : bs[3].x);
                float c2 = sigf(vf) * creg[j] + sigf(vi) * tanhf(vg);
                creg[j] = c2;
                cn[e] = c2;
                hn[e] = sigf(vo) * tanhf(c2);
            }
            size_t oidx = ((size_t)b * S_LEN + srow) * 2048 + dir * HDIM + hu0;
            *(float2*)(out + oidx) = make_float2(hn[0], hn[1]);

            *(__half2*)(hd + b * HDIM + hu0) =
                __half2(__float2half(hn[0]), __float2half(hn[1]));

            if (t == S_LEN - 1) {
                *(float2*)(out + OUT_HID  + (size_t)b * 2048 + dir * HDIM + hu0) = make_float2(hn[0], hn[1]);
                *(float2*)(out + OUT_CELL + (size_t)b * 2048 + dir * HDIM + hu0) = make_float2(cn[0], cn[1]);
            }
        }

        // ---- per-dir grid barrier ----
        __syncthreads();
        if (tid == 0) {
            __threadfence();
            atomicAdd(&g_bar[dir], 1u);
            unsigned tgt = 64u * (unsigned)(t + 1), v;
            do {
                asm volatile("ld.acquire.gpu.u32 %0, [%1];" : "=r"(v) : "l"(g_bar + dir));
            } while (v < tgt);
        }
        __syncthreads();
    }
}

// ---------------------------------------------------------------------------
// Host launcher
// ---------------------------------------------------------------------------
extern "C" void kernel_launch(void* const* d_in, const int* in_sizes, int n_in,
                              void* d_out, int out_size) {
    const int*   inputs = (const int*)d_in[0];
    const float* table  = (const float*)d_in[1];
    const float* Wx_f   = (const float*)d_in[2];
    const float* Wh_f   = (const float*)d_in[3];
    const float* b_f    = (const float*)d_in[4];
    const float* Wx_b   = (const float*)d_in[5];
    const float* Wh_b   = (const float*)d_in[6];
    const float* b_b    = (const float*)d_in[7];
    float* out = (float*)d_out;

    cudaFuncSetAttribute(k_prefill, cudaFuncAttributeMaxDynamicSharedMemorySize, P_SMEM);
    cudaFuncSetAttribute(k_recur,   cudaFuncAttributeMaxDynamicSharedMemorySize, R_SMEM);

    k_init<<<1024, 256>>>();
    k_embed<<<(MTOT * EDIM / 4 + 255) / 256, 256>>>(inputs, table);
    k_wsplit<<<dim3(NGATE / 32, EDIM / 32, 4), dim3(32, 8)>>>(Wx_f, Wh_f, Wx_b, Wh_b);
    k_prefill<<<dim3(NGATE / 128, MTOT / 128, 2), 256, P_SMEM>>>();
    k_recur<<<128, 256, R_SMEM>>>(b_f, b_b, out);
}

// round 13
// speedup vs baseline: 1.2359x; 1.2359x over previous
#include <cuda_runtime.h>
#include <cuda_fp16.h>
#include <cstdint>

// ---------------------------------------------------------------------------
// Problem constants
// ---------------------------------------------------------------------------
#define S_LEN   512
#define BATCH   64
#define EDIM    1024
#define HDIM    1024
#define NGATE   4096
#define MTOT    (S_LEN*BATCH)

#define OUT_HID  (67108864ull)
#define OUT_CELL (67108864ull + 131072ull)

// ---------------------------------------------------------------------------
// Static device scratch.
// Prefill: fp16 2-pass (x single, Wx hi/lo).  Recurrence: fp16 1-pass (Wh hi).
// ---------------------------------------------------------------------------
__device__ __half g_A[(size_t)MTOT * EDIM];
__device__ __half g_WxThi[2ull * NGATE * EDIM];          // [dir][n][k]
__device__ __half g_WxTlo[2ull * NGATE * EDIM];
__device__ __half g_WhThi[2ull * NGATE * HDIM];
__device__ __half g_WhTlo[2ull * NGATE * HDIM];          // kept (unused by recur)
__device__ float  g_Gx[2ull * S_LEN * BATCH * NGATE];    // [dir][s][b][n]
__device__ __half g_h[2 * 2 * BATCH * HDIM];             // [buf][dir][b][h]
__device__ unsigned g_bar[2];

// ---------------------------------------------------------------------------
// PTX helpers
// ---------------------------------------------------------------------------
__device__ __forceinline__ uint32_t smem_u32(const void* p) {
    return (uint32_t)__cvta_generic_to_shared(p);
}
__device__ __forceinline__ void cp16(void* dst, const void* src) {
    asm volatile("cp.async.cg.shared.global [%0], [%1], 16;\n"
                 :: "r"(smem_u32(dst)), "l"(src));
}
__device__ __forceinline__ void cp_commit() { asm volatile("cp.async.commit_group;\n"); }
template <int N>
__device__ __forceinline__ void cp_wait() { asm volatile("cp.async.wait_group %0;\n" :: "n"(N)); }

__device__ __forceinline__ void ldsm4(uint32_t r[4], uint32_t addr) {
    asm volatile("ldmatrix.sync.aligned.m8n8.x4.shared.b16 {%0,%1,%2,%3}, [%4];\n"
                 : "=r"(r[0]), "=r"(r[1]), "=r"(r[2]), "=r"(r[3]) : "r"(addr));
}
__device__ __forceinline__ void mma_f16(float c[4], const uint32_t a[4], const uint32_t b[2]) {
    asm volatile(
        "mma.sync.aligned.m16n8k16.row.col.f32.f16.f16.f32 "
        "{%0,%1,%2,%3}, {%4,%5,%6,%7}, {%8,%9}, {%0,%1,%2,%3};\n"
        : "+f"(c[0]), "+f"(c[1]), "+f"(c[2]), "+f"(c[3])
        : "r"(a[0]), "r"(a[1]), "r"(a[2]), "r"(a[3]), "r"(b[0]), "r"(b[1]));
}
__device__ __forceinline__ float sigf(float x) { return 1.0f / (1.0f + expf(-x)); }

// ---------------------------------------------------------------------------
// K0: zero state + barrier counters
// ---------------------------------------------------------------------------
__global__ void k_init() {
    int i = blockIdx.x * 256 + threadIdx.x;
    if (i < 2 * 2 * BATCH * HDIM) g_h[i] = __float2half(0.0f);
    if (i < 2) g_bar[i] = 0u;
}

// ---------------------------------------------------------------------------
// K1: embedding gather -> fp16.  Row m = s*64+b
// ---------------------------------------------------------------------------
__global__ void k_embed(const int* __restrict__ inputs, const float* __restrict__ table) {
    int idx = blockIdx.x * 256 + threadIdx.x;
    int m  = idx >> 8;
    int kk = (idx & 255) * 4;
    int s = m >> 6, b = m & 63;
    int tok = inputs[b * S_LEN + s];
    float4 v = *(const float4*)(table + (size_t)tok * EDIM + kk);
    size_t o = (size_t)m * EDIM + kk;
    *(__half2*)(g_A + o)     = __half2(__float2half(v.x), __float2half(v.y));
    *(__half2*)(g_A + o + 2) = __half2(__float2half(v.z), __float2half(v.w));
}

// ---------------------------------------------------------------------------
// K2: weight transpose + fp16 hi/lo split.  W[k][n] -> WT_hi/lo[n][k]
// ---------------------------------------------------------------------------
__global__ void k_wsplit(const float* __restrict__ w0, const float* __restrict__ w1,
                         const float* __restrict__ w2, const float* __restrict__ w3) {
    __shared__ float tile[32][33];
    int z = blockIdx.z;
    const float* W = (z == 0) ? w0 : (z == 1) ? w1 : (z == 2) ? w2 : w3;
    __half* Ohi = ((z & 1) ? g_WhThi : g_WxThi) + (size_t)(z >> 1) * NGATE * EDIM;
    __half* Olo = ((z & 1) ? g_WhTlo : g_WxTlo) + (size_t)(z >> 1) * NGATE * EDIM;
    int tx = threadIdx.x, ty = threadIdx.y;
    int n0 = blockIdx.x * 32, k0 = blockIdx.y * 32;
#pragma unroll
    for (int i = 0; i < 4; i++)
        tile[ty + i * 8][tx] = W[(size_t)(k0 + ty + i * 8) * NGATE + n0 + tx];
    __syncthreads();
#pragma unroll
    for (int i = 0; i < 4; i++) {
        int n = n0 + ty + i * 8;
        int k = k0 + tx;
        float v = tile[tx][ty + i * 8];
        __half hi = __float2half(v);
        Ohi[(size_t)n * EDIM + k] = hi;
        Olo[(size_t)n * EDIM + k] = __float2half(v - __half2float(hi));
    }
}

// ---------------------------------------------------------------------------
// K3: prefill GEMM  Gx[dir] = A @ WxT(dir)   (fp16 2-pass)
// 128x128 tile, BK=32, 2-stage (R11 config: proven fastest), 2 CTAs/SM.
// ---------------------------------------------------------------------------
#define P_SA   40
#define P_ARR  (128 * P_SA)
#define P_STG  (3 * P_ARR)
#define P_SMEM (2 * P_STG * 2)

__device__ __forceinline__ void prefill_load(
    __half* base, const __half* gBhi, const __half* gBlo,
    int tid, int m0, int n0, int k0)
{
#pragma unroll
    for (int j = 0; j < 2; j++) {
        int it = tid + j * 256;
        int r = it >> 2, ch = it & 3;
        size_t offA = (size_t)(m0 + r) * EDIM + k0 + ch * 8;
        cp16(base + r * P_SA + ch * 8, g_A + offA);
        size_t offB = (size_t)(n0 + r) * EDIM + k0 + ch * 8;
        cp16(base + P_ARR + r * P_SA + ch * 8,     gBhi + offB);
        cp16(base + 2 * P_ARR + r * P_SA + ch * 8, gBlo + offB);
    }
}

__global__ void __launch_bounds__(256, 2) k_prefill() {
    extern __shared__ __align__(16) char smraw[];
    __half* sm = (__half*)smraw;

    int tid = threadIdx.x, lane = tid & 31, warp = tid >> 5;
    int wm = warp >> 1, wn = warp & 1;
    int dir = blockIdx.z;
    int m0 = blockIdx.y * 128, n0 = blockIdx.x * 128;
    const __half* gBhi = g_WxThi + (size_t)dir * NGATE * EDIM;
    const __half* gBlo = g_WxTlo + (size_t)dir * NGATE * EDIM;

    int l8 = lane & 7, sel = lane >> 3;
    int aRow = wm * 32 + (lane & 15);
    int aK   = (lane >> 4) * 8;
    int bRow = wn * 64 + (sel >> 1) * 8 + l8;
    int bK   = (sel & 1) * 8;

    float acc[2][8][4];
#pragma unroll
    for (int a = 0; a < 2; a++)
#pragma unroll
        for (int b = 0; b < 8; b++)
#pragma unroll
            for (int c = 0; c < 4; c++) acc[a][b][c] = 0.0f;

    const int KT = EDIM / 32;   // 32
    prefill_load(sm,         gBhi, gBlo, tid, m0, n0, 0);
    cp_commit();
    prefill_load(sm + P_STG, gBhi, gBlo, tid, m0, n0, 32);
    cp_commit();

#pragma unroll 1
    for (int kt = 0; kt < KT; kt++) {
        if (kt + 1 < KT) cp_wait<1>(); else cp_wait<0>();
        __syncthreads();

        __half* base = sm + (kt & 1) * P_STG;
        uint32_t aB  = smem_u32(base);
        uint32_t bHb = aB + P_ARR * 2;
        uint32_t bLb = aB + 2 * P_ARR * 2;

#pragma unroll
        for (int ks = 0; ks < 32; ks += 16) {
            uint32_t ah[2][4];
#pragma unroll
            for (int mt = 0; mt < 2; mt++) {
                uint32_t ao = ((aRow + mt * 16) * P_SA + ks + aK) * 2;
                ldsm4(ah[mt], aB + ao);
            }
#pragma unroll
            for (int np = 0; np < 4; np++) {
                uint32_t bo = ((bRow + np * 16) * P_SA + ks + bK) * 2;
                uint32_t bh4[4], bl4[4];
                ldsm4(bh4, bHb + bo);
                ldsm4(bl4, bLb + bo);
#pragma unroll
                for (int mt = 0; mt < 2; mt++) {
                    mma_f16(acc[mt][np*2],   ah[mt], bh4 + 0);
                    mma_f16(acc[mt][np*2],   ah[mt], bl4 + 0);
                    mma_f16(acc[mt][np*2+1], ah[mt], bh4 + 2);
                    mma_f16(acc[mt][np*2+1], ah[mt], bl4 + 2);
                }
            }
        }
        __syncthreads();
        if (kt + 2 < KT)
            prefill_load(sm + (kt & 1) * P_STG, gBhi, gBlo, tid, m0, n0, (kt + 2) * 32);
        cp_commit();
    }

    float* C = g_Gx + (size_t)dir * S_LEN * BATCH * NGATE;
#pragma unroll
    for (int mt = 0; mt < 2; mt++) {
#pragma unroll
        for (int nt = 0; nt < 8; nt++) {
            int row = m0 + wm * 32 + mt * 16 + (lane >> 2);
            int col = n0 + wn * 64 + nt * 8 + 2 * (lane & 3);
            *(float2*)(C + (size_t)row * NGATE + col)       = make_float2(acc[mt][nt][0], acc[mt][nt][1]);
            *(float2*)(C + (size_t)(row + 8) * NGATE + col) = make_float2(acc[mt][nt][2], acc[mt][nt][3]);
        }
    }
}

// ---------------------------------------------------------------------------
// K4: persistent recurrence.  128 CTAs (64/dir), 256 thr.
// SINGLE-PASS Wh (fp16-rounded hi only), fully RESIDENT in smem (128KB).
// Streams ONLY h: 8KB chunks, 4-stage ring.  smem = 160KB.
// B row r -> weight row: gate=(r>>3)&3, hu=(r&7)|((r>>5)<<3).
// Each thread's 4 acc frags = 4 gates of the same hu pair -> LSTM in regs.
// ---------------------------------------------------------------------------
#define RES_W  131072
#define H_OFF  RES_W
#define R_SMEM (RES_W + 32768)     // 163840

__device__ __forceinline__ int r_grow(int r, int hu_base) {
    return ((r >> 3) & 3) * HDIM + hu_base + ((r & 7) | ((r >> 5) << 3));
}
__device__ __forceinline__ uint32_t r_sw(int r, int u) {
    return (uint32_t)(r * 128 + ((u ^ (r & 7)) << 4));
}

__device__ __forceinline__ void r_load_h(char* stg, const __half* hs, int tid, int k0) {
#pragma unroll
    for (int j = 0; j < 2; j++) {
        int it = tid + j * 256;
        int r = it >> 3, ch = it & 7;
        cp16(stg + r_sw(r, ch), hs + (size_t)r * HDIM + k0 + ch * 8);
    }
}

__global__ void __launch_bounds__(256, 1) k_recur(const float* __restrict__ bias_f,
                                                  const float* __restrict__ bias_b,
                                                  float* __restrict__ out) {
    extern __shared__ __align__(16) char smraw[];

    int tid = threadIdx.x, lane = tid & 31, warp = tid >> 5;
    int wm = warp >> 1, wn = warp & 1;            // 4 m-warps x 2 n-warps
    int dir = blockIdx.x >> 6;
    int hu_base = (blockIdx.x & 63) * 16;

    const __half* wH = g_WhThi + (size_t)dir * NGATE * HDIM;
    const float* bias = dir ? bias_b : bias_f;

    int l8 = lane & 7, sel = lane >> 3;
    int aRow = wm * 16 + (lane & 15);
    int aK   = (lane >> 4) * 8;
    int bRow = wn * 32 + (sel >> 1) * 8 + l8;
    int bK   = (sel & 1) * 8;

    int hu0 = hu_base + wn * 8 + 2 * (lane & 3);
    float2 bs[4];
#pragma unroll
    for (int g = 0; g < 4; g++)
        bs[g] = *(const float2*)(bias + g * HDIM + hu0);

    // ---- prologue: resident Wh-hi (16 chunks x 64 rows x 64 k) ----
    for (int slot = tid; slot < 16 * 512; slot += 256) {
        int c = slot >> 9, r = (slot >> 3) & 63, ch = slot & 7;
        cp16(smraw + c * 8192 + r_sw(r, ch),
             wH + (size_t)r_grow(r, hu_base) * HDIM + c * 64 + ch * 8);
    }
    cp_commit();
    cp_wait<0>();
    __syncthreads();

    float creg[4] = {0.f, 0.f, 0.f, 0.f};

#pragma unroll 1
    for (int t = 0; t < S_LEN; t++) {
        const __half* hs = g_h + (size_t)((t & 1) * 2 + dir) * BATCH * HDIM;

        int srow = dir ? (S_LEN - 1 - t) : t;
        const float* Gx = g_Gx + ((size_t)dir * S_LEN + srow) * BATCH * NGATE;
        float2 gx[2][4];
#pragma unroll
        for (int k = 0; k < 2; k++) {
            int b = wm * 16 + (lane >> 2) + k * 8;
#pragma unroll
            for (int g = 0; g < 4; g++)
                gx[k][g] = *(const float2*)(Gx + (size_t)b * NGATE + g * HDIM + hu0);
        }

        r_load_h(smraw + H_OFF,         hs, tid, 0);   cp_commit();
        r_load_h(smraw + H_OFF + 8192,  hs, tid, 64);  cp_commit();
        r_load_h(smraw + H_OFF + 16384, hs, tid, 128); cp_commit();

        float acc[4][4];
#pragma unroll
        for (int g = 0; g < 4; g++)
#pragma unroll
            for (int c = 0; c < 4; c++) acc[g][c] = 0.0f;

        const int KT = HDIM / 64;   // 16
#pragma unroll 1
        for (int kt = 0; kt < KT; kt++) {
            cp_wait<2>();
            __syncthreads();
            if (kt + 3 < KT)
                r_load_h(smraw + H_OFF + ((kt + 3) & 3) * 8192, hs, tid, (kt + 3) * 64);
            cp_commit();

            uint32_t resb = smem_u32(smraw) + kt * 8192;
            uint32_t aB   = smem_u32(smraw + H_OFF + (kt & 3) * 8192);

#pragma unroll
            for (int ks = 0; ks < 64; ks += 16) {
                uint32_t ao = r_sw(aRow, (ks + aK) >> 3);
                uint32_t ah[4];
                ldsm4(ah, aB + ao);
#pragma unroll
                for (int np = 0; np < 2; np++) {
                    int br = bRow + np * 16;
                    uint32_t bo = r_sw(br, (ks + bK) >> 3);
                    uint32_t bh4[4];
                    ldsm4(bh4, resb + bo);
                    mma_f16(acc[np*2],   ah, bh4 + 0);
                    mma_f16(acc[np*2+1], ah, bh4 + 2);
                }
            }
        }

        // ---- fused LSTM update ----
        __half* hd = g_h + (size_t)(((t + 1) & 1) * 2 + dir) * BATCH * HDIM;

#pragma unroll
        for (int k = 0; k < 2; k++) {
            int b = wm * 16 + (lane >> 2) + k * 8;
            float hn[2], cn[2];
#pragma unroll
            for (int e = 0; e < 2; e++) {
                int j = k * 2 + e;
                float vi = acc[0][j] + (e ? gx[k][0].y : gx[k][0].x) + (e ? bs[0].y : bs[0].x);
                float vf = acc[1][j] + (e ? gx[k][1].y : gx[k][1].x) + (e ? bs[1].y : bs[1].x);
                float vg = acc[2][j] + (e ? gx[k][2].y : gx[k][2].x) + (e ? bs[2].y : bs[2].x);
                float vo = acc[3][j] + (e ? gx[k][3].y : gx[k][3].x) + (e ? bs[3].y : bs[3].x);
                float c2 = sigf(vf) * creg[j] + sigf(vi) * tanhf(vg);
                creg[j] = c2;
                cn[e] = c2;
                hn[e] = sigf(vo) * tanhf(c2);
            }
            size_t oidx = ((size_t)b * S_LEN + srow) * 2048 + dir * HDIM + hu0;
            *(float2*)(out + oidx) = make_float2(hn[0], hn[1]);

            *(__half2*)(hd + b * HDIM + hu0) =
                __half2(__float2half(hn[0]), __float2half(hn[1]));

            if (t == S_LEN - 1) {
                *(float2*)(out + OUT_HID  + (size_t)b * 2048 + dir * HDIM + hu0) = make_float2(hn[0], hn[1]);
                *(float2*)(out + OUT_CELL + (size_t)b * 2048 + dir * HDIM + hu0) = make_float2(cn[0], cn[1]);
            }
        }

        // ---- per-dir grid barrier ----
        __syncthreads();
        if (tid == 0) {
            __threadfence();
            atomicAdd(&g_bar[dir], 1u);
            unsigned tgt = 64u * (unsigned)(t + 1), v;
            do {
                asm volatile("ld.acquire.gpu.u32 %0, [%1];" : "=r"(v) : "l"(g_bar + dir));
            } while (v < tgt);
        }
        __syncthreads();
    }
}

// ---------------------------------------------------------------------------
// Host launcher
// ---------------------------------------------------------------------------
extern "C" void kernel_launch(void* const* d_in, const int* in_sizes, int n_in,
                              void* d_out, int out_size) {
    const int*   inputs = (const int*)d_in[0];
    const float* table  = (const float*)d_in[1];
    const float* Wx_f   = (const float*)d_in[2];
    const float* Wh_f   = (const float*)d_in[3];
    const float* b_f    = (const float*)d_in[4];
    const float* Wx_b   = (const float*)d_in[5];
    const float* Wh_b   = (const float*)d_in[6];
    const float* b_b    = (const float*)d_in[7];
    float* out = (float*)d_out;

    cudaFuncSetAttribute(k_prefill, cudaFuncAttributeMaxDynamicSharedMemorySize, P_SMEM);
    cudaFuncSetAttribute(k_recur,   cudaFuncAttributeMaxDynamicSharedMemorySize, R_SMEM);

    k_init<<<1024, 256>>>();
    k_embed<<<(MTOT * EDIM / 4 + 255) / 256, 256>>>(inputs, table);
    k_wsplit<<<dim3(NGATE / 32, EDIM / 32, 4), dim3(32, 8)>>>(Wx_f, Wh_f, Wx_b, Wh_b);
    k_prefill<<<dim3(NGATE / 128, MTOT / 128, 2), 256, P_SMEM>>>();
    k_recur<<<128, 256, R_SMEM>>>(b_f, b_b, out);
}

// round 14
// speedup vs baseline: 1.5302x; 1.2381x over previous
#include <cuda_runtime.h>
#include <cuda_fp16.h>
#include <cstdint>

// ---------------------------------------------------------------------------
// Problem constants
// ---------------------------------------------------------------------------
#define S_LEN   512
#define BATCH   64
#define EDIM    1024
#define HDIM    1024
#define NGATE   4096
#define MTOT    (S_LEN*BATCH)

#define OUT_HID  (67108864ull)
#define OUT_CELL (67108864ull + 131072ull)

// ---------------------------------------------------------------------------
// Static device scratch.  All GEMMs fp16 single-pass (x, h, Wx, Wh fp16).
// ---------------------------------------------------------------------------
__device__ __half g_A[(size_t)MTOT * EDIM];
__device__ __half g_WxT[2ull * NGATE * EDIM];            // [dir][n][k]
__device__ __half g_WhT[2ull * NGATE * HDIM];
__device__ float  g_Gx[2ull * S_LEN * BATCH * NGATE];    // [dir][s][b][n]
__device__ __half g_h[2 * 2 * BATCH * HDIM];             // [buf][dir][b][h]
__device__ unsigned g_bar[2];

// ---------------------------------------------------------------------------
// PTX helpers
// ---------------------------------------------------------------------------
__device__ __forceinline__ uint32_t smem_u32(const void* p) {
    return (uint32_t)__cvta_generic_to_shared(p);
}
__device__ __forceinline__ void cp16(void* dst, const void* src) {
    asm volatile("cp.async.cg.shared.global [%0], [%1], 16;\n"
                 :: "r"(smem_u32(dst)), "l"(src));
}
__device__ __forceinline__ void cp_commit() { asm volatile("cp.async.commit_group;\n"); }
template <int N>
__device__ __forceinline__ void cp_wait() { asm volatile("cp.async.wait_group %0;\n" :: "n"(N)); }

__device__ __forceinline__ void ldsm4(uint32_t r[4], uint32_t addr) {
    asm volatile("ldmatrix.sync.aligned.m8n8.x4.shared.b16 {%0,%1,%2,%3}, [%4];\n"
                 : "=r"(r[0]), "=r"(r[1]), "=r"(r[2]), "=r"(r[3]) : "r"(addr));
}
__device__ __forceinline__ void mma_f16(float c[4], const uint32_t a[4], const uint32_t b[2]) {
    asm volatile(
        "mma.sync.aligned.m16n8k16.row.col.f32.f16.f16.f32 "
        "{%0,%1,%2,%3}, {%4,%5,%6,%7}, {%8,%9}, {%0,%1,%2,%3};\n"
        : "+f"(c[0]), "+f"(c[1]), "+f"(c[2]), "+f"(c[3])
        : "r"(a[0]), "r"(a[1]), "r"(a[2]), "r"(a[3]), "r"(b[0]), "r"(b[1]));
}
__device__ __forceinline__ float sigf(float x) { return 1.0f / (1.0f + expf(-x)); }

// ---------------------------------------------------------------------------
// K0: zero state + barrier counters
// ---------------------------------------------------------------------------
__global__ void k_init() {
    int i = blockIdx.x * 256 + threadIdx.x;
    if (i < 2 * 2 * BATCH * HDIM) g_h[i] = __float2half(0.0f);
    if (i < 2) g_bar[i] = 0u;
}

// ---------------------------------------------------------------------------
// K1: embedding gather -> fp16.  Row m = s*64+b
// ---------------------------------------------------------------------------
__global__ void k_embed(const int* __restrict__ inputs, const float* __restrict__ table) {
    int idx = blockIdx.x * 256 + threadIdx.x;
    int m  = idx >> 8;
    int kk = (idx & 255) * 4;
    int s = m >> 6, b = m & 63;
    int tok = inputs[b * S_LEN + s];
    float4 v = *(const float4*)(table + (size_t)tok * EDIM + kk);
    size_t o = (size_t)m * EDIM + kk;
    *(__half2*)(g_A + o)     = __half2(__float2half(v.x), __float2half(v.y));
    *(__half2*)(g_A + o + 2) = __half2(__float2half(v.z), __float2half(v.w));
}

// ---------------------------------------------------------------------------
// K2: weight transpose -> fp16.  W[k][n] -> WT[n][k]
// ---------------------------------------------------------------------------
__global__ void k_wsplit(const float* __restrict__ w0, const float* __restrict__ w1,
                         const float* __restrict__ w2, const float* __restrict__ w3) {
    __shared__ float tile[32][33];
    int z = blockIdx.z;
    const float* W = (z == 0) ? w0 : (z == 1) ? w1 : (z == 2) ? w2 : w3;
    __half* O = ((z & 1) ? g_WhT : g_WxT) + (size_t)(z >> 1) * NGATE * EDIM;
    int tx = threadIdx.x, ty = threadIdx.y;
    int n0 = blockIdx.x * 32, k0 = blockIdx.y * 32;
#pragma unroll
    for (int i = 0; i < 4; i++)
        tile[ty + i * 8][tx] = W[(size_t)(k0 + ty + i * 8) * NGATE + n0 + tx];
    __syncthreads();
#pragma unroll
    for (int i = 0; i < 4; i++) {
        int n = n0 + ty + i * 8;
        int k = k0 + tx;
        O[(size_t)n * EDIM + k] = __float2half(tile[tx][ty + i * 8]);
    }
}

// ---------------------------------------------------------------------------
// K3: prefill GEMM  Gx[dir] = A @ WxT(dir)   (fp16 1-pass)
// 128x128 tile, BK=32, 2-stage, 2 CTAs/SM; stage = A | B = 20KB.
// ---------------------------------------------------------------------------
#define P_SA   40
#define P_ARR  (128 * P_SA)
#define P_STG  (2 * P_ARR)
#define P_SMEM (2 * P_STG * 2)

__device__ __forceinline__ void prefill_load(
    __half* base, const __half* gB, int tid, int m0, int n0, int k0)
{
#pragma unroll
    for (int j = 0; j < 2; j++) {
        int it = tid + j * 256;
        int r = it >> 2, ch = it & 3;
        cp16(base + r * P_SA + ch * 8,
             g_A + (size_t)(m0 + r) * EDIM + k0 + ch * 8);
        cp16(base + P_ARR + r * P_SA + ch * 8,
             gB + (size_t)(n0 + r) * EDIM + k0 + ch * 8);
    }
}

__global__ void __launch_bounds__(256, 2) k_prefill() {
    extern __shared__ __align__(16) char smraw[];
    __half* sm = (__half*)smraw;

    int tid = threadIdx.x, lane = tid & 31, warp = tid >> 5;
    int wm = warp >> 1, wn = warp & 1;
    int dir = blockIdx.z;
    int m0 = blockIdx.y * 128, n0 = blockIdx.x * 128;
    const __half* gB = g_WxT + (size_t)dir * NGATE * EDIM;

    int l8 = lane & 7, sel = lane >> 3;
    int aRow = wm * 32 + (lane & 15);
    int aK   = (lane >> 4) * 8;
    int bRow = wn * 64 + (sel >> 1) * 8 + l8;
    int bK   = (sel & 1) * 8;

    float acc[2][8][4];
#pragma unroll
    for (int a = 0; a < 2; a++)
#pragma unroll
        for (int b = 0; b < 8; b++)
#pragma unroll
            for (int c = 0; c < 4; c++) acc[a][b][c] = 0.0f;

    const int KT = EDIM / 32;   // 32
    prefill_load(sm,         gB, tid, m0, n0, 0);
    cp_commit();
    prefill_load(sm + P_STG, gB, tid, m0, n0, 32);
    cp_commit();

#pragma unroll 1
    for (int kt = 0; kt < KT; kt++) {
        if (kt + 1 < KT) cp_wait<1>(); else cp_wait<0>();
        __syncthreads();

        __half* base = sm + (kt & 1) * P_STG;
        uint32_t aB = smem_u32(base);
        uint32_t bB = aB + P_ARR * 2;

#pragma unroll
        for (int ks = 0; ks < 32; ks += 16) {
            uint32_t ah[2][4];
#pragma unroll
            for (int mt = 0; mt < 2; mt++) {
                uint32_t ao = ((aRow + mt * 16) * P_SA + ks + aK) * 2;
                ldsm4(ah[mt], aB + ao);
            }
#pragma unroll
            for (int np = 0; np < 4; np++) {
                uint32_t bo = ((bRow + np * 16) * P_SA + ks + bK) * 2;
                uint32_t b4[4];
                ldsm4(b4, bB + bo);
#pragma unroll
                for (int mt = 0; mt < 2; mt++) {
                    mma_f16(acc[mt][np*2],   ah[mt], b4 + 0);
                    mma_f16(acc[mt][np*2+1], ah[mt], b4 + 2);
                }
            }
        }
        __syncthreads();
        if (kt + 2 < KT)
            prefill_load(sm + (kt & 1) * P_STG, gB, tid, m0, n0, (kt + 2) * 32);
        cp_commit();
    }

    float* C = g_Gx + (size_t)dir * S_LEN * BATCH * NGATE;
#pragma unroll
    for (int mt = 0; mt < 2; mt++) {
#pragma unroll
        for (int nt = 0; nt < 8; nt++) {
            int row = m0 + wm * 32 + mt * 16 + (lane >> 2);
            int col = n0 + wn * 64 + nt * 8 + 2 * (lane & 3);
            *(float2*)(C + (size_t)row * NGATE + col)       = make_float2(acc[mt][nt][0], acc[mt][nt][1]);
            *(float2*)(C + (size_t)(row + 8) * NGATE + col) = make_float2(acc[mt][nt][2], acc[mt][nt][3]);
        }
    }
}

// ---------------------------------------------------------------------------
// K4: persistent recurrence.  128 CTAs (64/dir), 256 thr.
// Wh fp16 single-pass, fully resident (128KB).  h streamed in 8 x 16KB
// chunks (BK=128), 4-stage ring -> half the syncs of BK=64.
// B row r -> weight row: gate=(r>>3)&3, hu=(r&7)|((r>>5)<<3).
// ---------------------------------------------------------------------------
#define RES_W  131072
#define H_OFF  RES_W
#define H_STGB 16384
#define R_SMEM (RES_W + 4 * H_STGB)    // 196608

__device__ __forceinline__ int r_grow(int r, int hu_base) {
    return ((r >> 3) & 3) * HDIM + hu_base + ((r & 7) | ((r >> 5) << 3));
}
__device__ __forceinline__ uint32_t r_sw(int r, int u) {
    return (uint32_t)(r * 128 + ((u ^ (r & 7)) << 4));
}

// load 16KB h chunk (rows 0..63, k0..k0+127) as two swizzled 8KB sub-blocks
__device__ __forceinline__ void r_load_h(char* stg, const __half* hs, int tid, int k0) {
#pragma unroll
    for (int j = 0; j < 4; j++) {
        int slot = tid + j * 256;              // 1024 slots
        int r = slot >> 4, u = slot & 15;
        int sub = u >> 3, unit = u & 7;
        cp16(stg + sub * 8192 + r_sw(r, unit),
             hs + (size_t)r * HDIM + k0 + u * 8);
    }
}

__global__ void __launch_bounds__(256, 1) k_recur(const float* __restrict__ bias_f,
                                                  const float* __restrict__ bias_b,
                                                  float* __restrict__ out) {
    extern __shared__ __align__(16) char smraw[];

    int tid = threadIdx.x, lane = tid & 31, warp = tid >> 5;
    int wm = warp >> 1, wn = warp & 1;            // 4 m-warps x 2 n-warps
    int dir = blockIdx.x >> 6;
    int hu_base = (blockIdx.x & 63) * 16;

    const __half* wH = g_WhT + (size_t)dir * NGATE * HDIM;
    const float* bias = dir ? bias_b : bias_f;

    int l8 = lane & 7, sel = lane >> 3;
    int aRow = wm * 16 + (lane & 15);
    int aK   = (lane >> 4) * 8;
    int bRow = wn * 32 + (sel >> 1) * 8 + l8;
    int bK   = (sel & 1) * 8;

    int hu0 = hu_base + wn * 8 + 2 * (lane & 3);
    float2 bs[4];
#pragma unroll
    for (int g = 0; g < 4; g++)
        bs[g] = *(const float2*)(bias + g * HDIM + hu0);

    // ---- prologue: resident Wh (16 chunks x 64 rows x 64 k) ----
    for (int slot = tid; slot < 16 * 512; slot += 256) {
        int c = slot >> 9, r = (slot >> 3) & 63, ch = slot & 7;
        cp16(smraw + c * 8192 + r_sw(r, ch),
             wH + (size_t)r_grow(r, hu_base) * HDIM + c * 64 + ch * 8);
    }
    cp_commit();
    cp_wait<0>();
    __syncthreads();

    float creg[4] = {0.f, 0.f, 0.f, 0.f};

#pragma unroll 1
    for (int t = 0; t < S_LEN; t++) {
        const __half* hs = g_h + (size_t)((t & 1) * 2 + dir) * BATCH * HDIM;

        int srow = dir ? (S_LEN - 1 - t) : t;
        const float* Gx = g_Gx + ((size_t)dir * S_LEN + srow) * BATCH * NGATE;
        float2 gx[2][4];
#pragma unroll
        for (int k = 0; k < 2; k++) {
            int b = wm * 16 + (lane >> 2) + k * 8;
#pragma unroll
            for (int g = 0; g < 4; g++)
                gx[k][g] = *(const float2*)(Gx + (size_t)b * NGATE + g * HDIM + hu0);
        }

        r_load_h(smraw + H_OFF,              hs, tid, 0);   cp_commit();
        r_load_h(smraw + H_OFF + H_STGB,     hs, tid, 128); cp_commit();
        r_load_h(smraw + H_OFF + 2 * H_STGB, hs, tid, 256); cp_commit();

        float acc[4][4];
#pragma unroll
        for (int g = 0; g < 4; g++)
#pragma unroll
            for (int c = 0; c < 4; c++) acc[g][c] = 0.0f;

        const int KT = HDIM / 128;   // 8
#pragma unroll 1
        for (int kt = 0; kt < KT; kt++) {
            cp_wait<2>();
            __syncthreads();
            if (kt + 3 < KT)
                r_load_h(smraw + H_OFF + ((kt + 3) & 3) * H_STGB, hs, tid, (kt + 3) * 128);
            cp_commit();

            uint32_t aBase = smem_u32(smraw + H_OFF + (kt & 3) * H_STGB);

#pragma unroll
            for (int ks = 0; ks < 128; ks += 16) {
                uint32_t resb = smem_u32(smraw) + (kt * 2 + (ks >> 6)) * 8192;
                uint32_t aB   = aBase + (ks >> 6) * 8192;
                int ksl = ks & 63;
                uint32_t ao = r_sw(aRow, (ksl + aK) >> 3);
                uint32_t ah[4];
                ldsm4(ah, aB + ao);
#pragma unroll
                for (int np = 0; np < 2; np++) {
                    int br = bRow + np * 16;
                    uint32_t bo = r_sw(br, (ksl + bK) >> 3);
                    uint32_t b4[4];
                    ldsm4(b4, resb + bo);
                    mma_f16(acc[np*2],   ah, b4 + 0);
                    mma_f16(acc[np*2+1], ah, b4 + 2);
                }
            }
        }

        // ---- fused LSTM update ----
        __half* hd = g_h + (size_t)(((t + 1) & 1) * 2 + dir) * BATCH * HDIM;

#pragma unroll
        for (int k = 0; k < 2; k++) {
            int b = wm * 16 + (lane >> 2) + k * 8;
            float hn[2], cn[2];
#pragma unroll
            for (int e = 0; e < 2; e++) {
                int j = k * 2 + e;
                float vi = acc[0][j] + (e ? gx[k][0].y : gx[k][0].x) + (e ? bs[0].y : bs[0].x);
                float vf = acc[1][j] + (e ? gx[k][1].y : gx[k][1].x) + (e ? bs[1].y : bs[1].x);
                float vg = acc[2][j] + (e ? gx[k][2].y : gx[k][2].x) + (e ? bs[2].y : bs[2].x);
                float vo = acc[3][j] + (e ? gx[k][3].y : gx[k][3].x) + (e ? bs[3].y : bs[3].x);
                float c2 = sigf(vf) * creg[j] + sigf(vi) * tanhf(vg);
                creg[j] = c2;
                cn[e] = c2;
                hn[e] = sigf(vo) * tanhf(c2);
            }
            size_t oidx = ((size_t)b * S_LEN + srow) * 2048 + dir * HDIM + hu0;
            *(float2*)(out + oidx) = make_float2(hn[0], hn[1]);

            *(__half2*)(hd + b * HDIM + hu0) =
                __half2(__float2half(hn[0]), __float2half(hn[1]));

            if (t == S_LEN - 1) {
                *(float2*)(out + OUT_HID  + (size_t)b * 2048 + dir * HDIM + hu0) = make_float2(hn[0], hn[1]);
                *(float2*)(out + OUT_CELL + (size_t)b * 2048 + dir * HDIM + hu0) = make_float2(cn[0], cn[1]);
            }
        }

        // ---- per-dir grid barrier ----
        __syncthreads();
        if (tid == 0) {
            __threadfence();
            atomicAdd(&g_bar[dir], 1u);
            unsigned tgt = 64u * (unsigned)(t + 1), v;
            do {
                asm volatile("ld.acquire.gpu.u32 %0, [%1];" : "=r"(v) : "l"(g_bar + dir));
            } while (v < tgt);
        }
        __syncthreads();
    }
}

// ---------------------------------------------------------------------------
// Host launcher
// ---------------------------------------------------------------------------
extern "C" void kernel_launch(void* const* d_in, const int* in_sizes, int n_in,
                              void* d_out, int out_size) {
    const int*   inputs = (const int*)d_in[0];
    const float* table  = (const float*)d_in[1];
    const float* Wx_f   = (const float*)d_in[2];
    const float* Wh_f   = (const float*)d_in[3];
    const float* b_f    = (const float*)d_in[4];
    const float* Wx_b   = (const float*)d_in[5];
    const float* Wh_b   = (const float*)d_in[6];
    const float* b_b    = (const float*)d_in[7];
    float* out = (float*)d_out;

    cudaFuncSetAttribute(k_prefill, cudaFuncAttributeMaxDynamicSharedMemorySize, P_SMEM);
    cudaFuncSetAttribute(k_recur,   cudaFuncAttributeMaxDynamicSharedMemorySize, R_SMEM);

    k_init<<<1024, 256>>>();
    k_embed<<<(MTOT * EDIM / 4 + 255) / 256, 256>>>(inputs, table);
    k_wsplit<<<dim3(NGATE / 32, EDIM / 32, 4), dim3(32, 8)>>>(Wx_f, Wh_f, Wx_b, Wh_b);
    k_prefill<<<dim3(NGATE / 128, MTOT / 128, 2), 256, P_SMEM>>>();
    k_recur<<<128, 256, R_SMEM>>>(b_f, b_b, out);
}

// round 15
// speedup vs baseline: 1.5482x; 1.0118x over previous
#include <cuda_runtime.h>
#include <cuda_fp16.h>
#include <cstdint>

// ---------------------------------------------------------------------------
// Problem constants
// ---------------------------------------------------------------------------
#define S_LEN   512
#define BATCH   64
#define EDIM    1024
#define HDIM    1024
#define NGATE   4096
#define MTOT    (S_LEN*BATCH)

#define OUT_HID  (67108864ull)
#define OUT_CELL (67108864ull + 131072ull)

// ---------------------------------------------------------------------------
// Static device scratch.  All GEMMs fp16 single-pass; Gx stored fp16.
// ---------------------------------------------------------------------------
__device__ __half g_A[(size_t)MTOT * EDIM];
__device__ __half g_WxT[2ull * NGATE * EDIM];            // [dir][n][k]
__device__ __half g_WhT[2ull * NGATE * HDIM];
__device__ __half g_Gx[2ull * S_LEN * BATCH * NGATE];    // [dir][s][b][n] fp16
__device__ __half g_h[2 * 2 * BATCH * HDIM];             // [buf][dir][b][h]
__device__ unsigned g_bar[2];

// ---------------------------------------------------------------------------
// PTX helpers
// ---------------------------------------------------------------------------
__device__ __forceinline__ uint32_t smem_u32(const void* p) {
    return (uint32_t)__cvta_generic_to_shared(p);
}
__device__ __forceinline__ void cp16(void* dst, const void* src) {
    asm volatile("cp.async.cg.shared.global [%0], [%1], 16;\n"
                 :: "r"(smem_u32(dst)), "l"(src));
}
__device__ __forceinline__ void cp_commit() { asm volatile("cp.async.commit_group;\n"); }
template <int N>
__device__ __forceinline__ void cp_wait() { asm volatile("cp.async.wait_group %0;\n" :: "n"(N)); }

__device__ __forceinline__ void ldsm4(uint32_t r[4], uint32_t addr) {
    asm volatile("ldmatrix.sync.aligned.m8n8.x4.shared.b16 {%0,%1,%2,%3}, [%4];\n"
                 : "=r"(r[0]), "=r"(r[1]), "=r"(r[2]), "=r"(r[3]) : "r"(addr));
}
__device__ __forceinline__ void mma_f16(float c[4], const uint32_t a[4], const uint32_t b[2]) {
    asm volatile(
        "mma.sync.aligned.m16n8k16.row.col.f32.f16.f16.f32 "
        "{%0,%1,%2,%3}, {%4,%5,%6,%7}, {%8,%9}, {%0,%1,%2,%3};\n"
        : "+f"(c[0]), "+f"(c[1]), "+f"(c[2]), "+f"(c[3])
        : "r"(a[0]), "r"(a[1]), "r"(a[2]), "r"(a[3]), "r"(b[0]), "r"(b[1]));
}
__device__ __forceinline__ float sigf(float x) { return 1.0f / (1.0f + expf(-x)); }

// ---------------------------------------------------------------------------
// K0: zero state + barrier counters
// ---------------------------------------------------------------------------
__global__ void k_init() {
    int i = blockIdx.x * 256 + threadIdx.x;
    if (i < 2 * 2 * BATCH * HDIM) g_h[i] = __float2half(0.0f);
    if (i < 2) g_bar[i] = 0u;
}

// ---------------------------------------------------------------------------
// K1: embedding gather -> fp16.  Row m = s*64+b
// ---------------------------------------------------------------------------
__global__ void k_embed(const int* __restrict__ inputs, const float* __restrict__ table) {
    int idx = blockIdx.x * 256 + threadIdx.x;
    int m  = idx >> 8;
    int kk = (idx & 255) * 4;
    int s = m >> 6, b = m & 63;
    int tok = inputs[b * S_LEN + s];
    float4 v = *(const float4*)(table + (size_t)tok * EDIM + kk);
    size_t o = (size_t)m * EDIM + kk;
    *(__half2*)(g_A + o)     = __half2(__float2half(v.x), __float2half(v.y));
    *(__half2*)(g_A + o + 2) = __half2(__float2half(v.z), __float2half(v.w));
}

// ---------------------------------------------------------------------------
// K2: weight transpose -> fp16.  W[k][n] -> WT[n][k]
// ---------------------------------------------------------------------------
__global__ void k_wsplit(const float* __restrict__ w0, const float* __restrict__ w1,
                         const float* __restrict__ w2, const float* __restrict__ w3) {
    __shared__ float tile[32][33];
    int z = blockIdx.z;
    const float* W = (z == 0) ? w0 : (z == 1) ? w1 : (z == 2) ? w2 : w3;
    __half* O = ((z & 1) ? g_WhT : g_WxT) + (size_t)(z >> 1) * NGATE * EDIM;
    int tx = threadIdx.x, ty = threadIdx.y;
    int n0 = blockIdx.x * 32, k0 = blockIdx.y * 32;
#pragma unroll
    for (int i = 0; i < 4; i++)
        tile[ty + i * 8][tx] = W[(size_t)(k0 + ty + i * 8) * NGATE + n0 + tx];
    __syncthreads();
#pragma unroll
    for (int i = 0; i < 4; i++) {
        int n = n0 + ty + i * 8;
        int k = k0 + tx;
        O[(size_t)n * EDIM + k] = __float2half(tile[tx][ty + i * 8]);
    }
}

// ---------------------------------------------------------------------------
// K3: prefill GEMM  Gx[dir] = A @ WxT(dir)   (fp16 1-pass)
// 256x128 tile (M=256 tokens), 512 threads (4m x 4n warps), BK=32, 2-stage.
// Per-CTA traffic halves vs 128x128.  smem = 60KB.
// ---------------------------------------------------------------------------
#define P_SA    40
#define P_ARR_A (256 * P_SA)
#define P_ARR_B (128 * P_SA)
#define P_STG   (P_ARR_A + P_ARR_B)
#define P_SMEM  (2 * P_STG * 2)

__device__ __forceinline__ void prefill_load(
    __half* base, const __half* gB, int tid, int m0, int n0, int k0)
{
#pragma unroll
    for (int j = 0; j < 2; j++) {
        int it = tid + j * 512;
        int r = it >> 2, ch = it & 3;
        cp16(base + r * P_SA + ch * 8,
             g_A + (size_t)(m0 + r) * EDIM + k0 + ch * 8);
    }
    {
        int r = tid >> 2, ch = tid & 3;
        if (r < 128)
            cp16(base + P_ARR_A + r * P_SA + ch * 8,
                 gB + (size_t)(n0 + r) * EDIM + k0 + ch * 8);
    }
}

__global__ void __launch_bounds__(512, 1) k_prefill() {
    extern __shared__ __align__(16) char smraw[];
    __half* sm = (__half*)smraw;

    int tid = threadIdx.x, lane = tid & 31, warp = tid >> 5;
    int wm = warp >> 2, wn = warp & 3;            // 4 m-warps x 4 n-warps
    int dir = blockIdx.z;
    int m0 = blockIdx.y * 256, n0 = blockIdx.x * 128;
    const __half* gB = g_WxT + (size_t)dir * NGATE * EDIM;

    int l8 = lane & 7, sel = lane >> 3;
    int aRow = wm * 64 + (lane & 15);
    int aK   = (lane >> 4) * 8;
    int bRow = wn * 32 + (sel >> 1) * 8 + l8;
    int bK   = (sel & 1) * 8;

    float acc[4][4][4];
#pragma unroll
    for (int a = 0; a < 4; a++)
#pragma unroll
        for (int b = 0; b < 4; b++)
#pragma unroll
            for (int c = 0; c < 4; c++) acc[a][b][c] = 0.0f;

    const int KT = EDIM / 32;   // 32
    prefill_load(sm,         gB, tid, m0, n0, 0);
    cp_commit();
    prefill_load(sm + P_STG, gB, tid, m0, n0, 32);
    cp_commit();

#pragma unroll 1
    for (int kt = 0; kt < KT; kt++) {
        if (kt + 1 < KT) cp_wait<1>(); else cp_wait<0>();
        __syncthreads();

        __half* base = sm + (kt & 1) * P_STG;
        uint32_t aB = smem_u32(base);
        uint32_t bB = aB + P_ARR_A * 2;

#pragma unroll
        for (int ks = 0; ks < 32; ks += 16) {
            uint32_t ah[4][4];
#pragma unroll
            for (int mt = 0; mt < 4; mt++) {
                uint32_t ao = ((aRow + mt * 16) * P_SA + ks + aK) * 2;
                ldsm4(ah[mt], aB + ao);
            }
#pragma unroll
            for (int np = 0; np < 2; np++) {
                uint32_t bo = ((bRow + np * 16) * P_SA + ks + bK) * 2;
                uint32_t b4[4];
                ldsm4(b4, bB + bo);
#pragma unroll
                for (int mt = 0; mt < 4; mt++) {
                    mma_f16(acc[mt][np*2],   ah[mt], b4 + 0);
                    mma_f16(acc[mt][np*2+1], ah[mt], b4 + 2);
                }
            }
        }
        __syncthreads();
        if (kt + 2 < KT)
            prefill_load(sm + (kt & 1) * P_STG, gB, tid, m0, n0, (kt + 2) * 32);
        cp_commit();
    }

    __half* C = g_Gx + (size_t)dir * S_LEN * BATCH * NGATE;
#pragma unroll
    for (int mt = 0; mt < 4; mt++) {
#pragma unroll
        for (int nt = 0; nt < 4; nt++) {
            int row = m0 + wm * 64 + mt * 16 + (lane >> 2);
            int col = n0 + wn * 32 + nt * 8 + 2 * (lane & 3);
            *(__half2*)(C + (size_t)row * NGATE + col) =
                __floats2half2_rn(acc[mt][nt][0], acc[mt][nt][1]);
            *(__half2*)(C + (size_t)(row + 8) * NGATE + col) =
                __floats2half2_rn(acc[mt][nt][2], acc[mt][nt][3]);
        }
    }
}

// ---------------------------------------------------------------------------
// K4: persistent recurrence.  128 CTAs (64/dir), 256 thr.  (R14 config)
// Wh fp16 single-pass, fully resident (128KB).  h streamed in 8 x 16KB
// chunks (BK=128), 4-stage ring.  Gx read as fp16.
// ---------------------------------------------------------------------------
#define RES_W  131072
#define H_OFF  RES_W
#define H_STGB 16384
#define R_SMEM (RES_W + 4 * H_STGB)    // 196608

__device__ __forceinline__ int r_grow(int r, int hu_base) {
    return ((r >> 3) & 3) * HDIM + hu_base + ((r & 7) | ((r >> 5) << 3));
}
__device__ __forceinline__ uint32_t r_sw(int r, int u) {
    return (uint32_t)(r * 128 + ((u ^ (r & 7)) << 4));
}

__device__ __forceinline__ void r_load_h(char* stg, const __half* hs, int tid, int k0) {
#pragma unroll
    for (int j = 0; j < 4; j++) {
        int slot = tid + j * 256;              // 1024 slots
        int r = slot >> 4, u = slot & 15;
        int sub = u >> 3, unit = u & 7;
        cp16(stg + sub * 8192 + r_sw(r, unit),
             hs + (size_t)r * HDIM + k0 + u * 8);
    }
}

__global__ void __launch_bounds__(256, 1) k_recur(const float* __restrict__ bias_f,
                                                  const float* __restrict__ bias_b,
                                                  float* __restrict__ out) {
    extern __shared__ __align__(16) char smraw[];

    int tid = threadIdx.x, lane = tid & 31, warp = tid >> 5;
    int wm = warp >> 1, wn = warp & 1;            // 4 m-warps x 2 n-warps
    int dir = blockIdx.x >> 6;
    int hu_base = (blockIdx.x & 63) * 16;

    const __half* wH = g_WhT + (size_t)dir * NGATE * HDIM;
    const float* bias = dir ? bias_b : bias_f;

    int l8 = lane & 7, sel = lane >> 3;
    int aRow = wm * 16 + (lane & 15);
    int aK   = (lane >> 4) * 8;
    int bRow = wn * 32 + (sel >> 1) * 8 + l8;
    int bK   = (sel & 1) * 8;

    int hu0 = hu_base + wn * 8 + 2 * (lane & 3);
    float2 bs[4];
#pragma unroll
    for (int g = 0; g < 4; g++)
        bs[g] = *(const float2*)(bias + g * HDIM + hu0);

    // ---- prologue: resident Wh (16 chunks x 64 rows x 64 k) ----
    for (int slot = tid; slot < 16 * 512; slot += 256) {
        int c = slot >> 9, r = (slot >> 3) & 63, ch = slot & 7;
        cp16(smraw + c * 8192 + r_sw(r, ch),
             wH + (size_t)r_grow(r, hu_base) * HDIM + c * 64 + ch * 8);
    }
    cp_commit();
    cp_wait<0>();
    __syncthreads();

    float creg[4] = {0.f, 0.f, 0.f, 0.f};

#pragma unroll 1
    for (int t = 0; t < S_LEN; t++) {
        const __half* hs = g_h + (size_t)((t & 1) * 2 + dir) * BATCH * HDIM;

        int srow = dir ? (S_LEN - 1 - t) : t;
        const __half* Gx = g_Gx + ((size_t)dir * S_LEN + srow) * BATCH * NGATE;
        float2 gx[2][4];
#pragma unroll
        for (int k = 0; k < 2; k++) {
            int b = wm * 16 + (lane >> 2) + k * 8;
#pragma unroll
            for (int g = 0; g < 4; g++)
                gx[k][g] = __half22float2(*(const __half2*)(Gx + (size_t)b * NGATE + g * HDIM + hu0));
        }

        r_load_h(smraw + H_OFF,              hs, tid, 0);   cp_commit();
        r_load_h(smraw + H_OFF + H_STGB,     hs, tid, 128); cp_commit();
        r_load_h(smraw + H_OFF + 2 * H_STGB, hs, tid, 256); cp_commit();

        float acc[4][4];
#pragma unroll
        for (int g = 0; g < 4; g++)
#pragma unroll
            for (int c = 0; c < 4; c++) acc[g][c] = 0.0f;

        const int KT = HDIM / 128;   // 8
#pragma unroll 1
        for (int kt = 0; kt < KT; kt++) {
            cp_wait<2>();
            __syncthreads();
            if (kt + 3 < KT)
                r_load_h(smraw + H_OFF + ((kt + 3) & 3) * H_STGB, hs, tid, (kt + 3) * 128);
            cp_commit();

            uint32_t aBase = smem_u32(smraw + H_OFF + (kt & 3) * H_STGB);

#pragma unroll
            for (int ks = 0; ks < 128; ks += 16) {
                uint32_t resb = smem_u32(smraw) + (kt * 2 + (ks >> 6)) * 8192;
                uint32_t aB   = aBase + (ks >> 6) * 8192;
                int ksl = ks & 63;
                uint32_t ao = r_sw(aRow, (ksl + aK) >> 3);
                uint32_t ah[4];
                ldsm4(ah, aB + ao);
#pragma unroll
                for (int np = 0; np < 2; np++) {
                    int br = bRow + np * 16;
                    uint32_t bo = r_sw(br, (ksl + bK) >> 3);
                    uint32_t b4[4];
                    ldsm4(b4, resb + bo);
                    mma_f16(acc[np*2],   ah, b4 + 0);
                    mma_f16(acc[np*2+1], ah, b4 + 2);
                }
            }
        }

        // ---- fused LSTM update ----
        __half* hd = g_h + (size_t)(((t + 1) & 1) * 2 + dir) * BATCH * HDIM;

#pragma unroll
        for (int k = 0; k < 2; k++) {
            int b = wm * 16 + (lane >> 2) + k * 8;
            float hn[2], cn[2];
#pragma unroll
            for (int e = 0; e < 2; e++) {
                int j = k * 2 + e;
                float vi = acc[0][j] + (e ? gx[k][0].y : gx[k][0].x) + (e ? bs[0].y : bs[0].x);
                float vf = acc[1][j] + (e ? gx[k][1].y : gx[k][1].x) + (e ? bs[1].y : bs[1].x);
                float vg = acc[2][j] + (e ? gx[k][2].y : gx[k][2].x) + (e ? bs[2].y : bs[2].x);
                float vo = acc[3][j] + (e ? gx[k][3].y : gx[k][3].x) + (e ? bs[3].y : bs[3].x);
                float c2 = sigf(vf) * creg[j] + sigf(vi) * tanhf(vg);
                creg[j] = c2;
                cn[e] = c2;
                hn[e] = sigf(vo) * tanhf(c2);
            }
            size_t oidx = ((size_t)b * S_LEN + srow) * 2048 + dir * HDIM + hu0;
            *(float2*)(out + oidx) = make_float2(hn[0], hn[1]);

            *(__half2*)(hd + b * HDIM + hu0) =
                __half2(__float2half(hn[0]), __float2half(hn[1]));

            if (t == S_LEN - 1) {
                *(float2*)(out + OUT_HID  + (size_t)b * 2048 + dir * HDIM + hu0) = make_float2(hn[0], hn[1]);
                *(float2*)(out + OUT_CELL + (size_t)b * 2048 + dir * HDIM + hu0) = make_float2(cn[0], cn[1]);
            }
        }

        // ---- per-dir grid barrier ----
        __syncthreads();
        if (tid == 0) {
            __threadfence();
            atomicAdd(&g_bar[dir], 1u);
            unsigned tgt = 64u * (unsigned)(t + 1), v;
            do {
                asm volatile("ld.acquire.gpu.u32 %0, [%1];" : "=r"(v) : "l"(g_bar + dir));
            } while (v < tgt);
        }
        __syncthreads();
    }
}

// ---------------------------------------------------------------------------
// Host launcher
// ---------------------------------------------------------------------------
extern "C" void kernel_launch(void* const* d_in, const int* in_sizes, int n_in,
                              void* d_out, int out_size) {
    const int*   inputs = (const int*)d_in[0];
    const float* table  = (const float*)d_in[1];
    const float* Wx_f   = (const float*)d_in[2];
    const float* Wh_f   = (const float*)d_in[3];
    const float* b_f    = (const float*)d_in[4];
    const float* Wx_b   = (const float*)d_in[5];
    const float* Wh_b   = (const float*)d_in[6];
    const float* b_b    = (const float*)d_in[7];
    float* out = (float*)d_out;

    cudaFuncSetAttribute(k_prefill, cudaFuncAttributeMaxDynamicSharedMemorySize, P_SMEM);
    cudaFuncSetAttribute(k_recur,   cudaFuncAttributeMaxDynamicSharedMemorySize, R_SMEM);

    k_init<<<1024, 256>>>();
    k_embed<<<(MTOT * EDIM / 4 + 255) / 256, 256>>>(inputs, table);
    k_wsplit<<<dim3(NGATE / 32, EDIM / 32, 4), dim3(32, 8)>>>(Wx_f, Wh_f, Wx_b, Wh_b);
    k_prefill<<<dim3(NGATE / 128, MTOT / 256, 2), 512, P_SMEM>>>();
    k_recur<<<128, 256, R_SMEM>>>(b_f, b_b, out);
}